// round 8
// baseline (speedup 1.0000x reference)
#include <cuda_runtime.h>

// ============================================================================
// AdditiveAttention: out = softmax_k( sum_h w_v[h]*tanh(qW_q + kW_k) ) @ V
// B=16, NQ=64, NK=512, QS=KS=H=VD=256, fp32.
//
// R8 restructure of attn_kernel (R7 was smem-crossbar bound):
//   Old: warp = (1 query, 32 keys), 3 LDS.128 per 4 elements (2 broadcasts).
//   New: warp = (8 queries, 32 fixed keys), keys staged in h-chunks of 32
//        (all 512 keys resident per chunk, double-buffered cp.async).
//        10 LDS.128 per 32 elements -> 2.4x less crossbar traffic,
//        kernel becomes MUFU(tanh)-bound.
// ============================================================================

// scratch (allocation-free rule -> __device__ globals)
__device__ float g_qh[16 * 64 * 256];    // 4 MB: queries @ W_q
__device__ float g_kh[16 * 512 * 256];   // 8 MB: keys @ W_k

__device__ __forceinline__ float tanh_fast(float x) {
    float r; asm("tanh.approx.f32 %0, %1;" : "=f"(r) : "f"(x)); return r;
}
__device__ __forceinline__ float ex2_fast(float x) {
    float r; asm("ex2.approx.f32 %0, %1;" : "=f"(r) : "f"(x)); return r;
}
__device__ __forceinline__ float rcp_fast(float x) {
    float r; asm("rcp.approx.f32 %0, %1;" : "=f"(r) : "f"(x)); return r;
}
__device__ __forceinline__ void cp_async16(void* smem_dst, const void* gmem_src) {
    unsigned s = (unsigned)__cvta_generic_to_shared(smem_dst);
    asm volatile("cp.async.cg.shared.global [%0], [%1], 16;\n" :: "r"(s), "l"(gmem_src));
}
__device__ __forceinline__ void cp_async_commit() {
    asm volatile("cp.async.commit_group;\n" ::);
}
__device__ __forceinline__ void cp_async_wait1() {
    asm volatile("cp.async.wait_group 1;\n" ::);
}
__device__ __forceinline__ void cp_async_wait0() {
    asm volatile("cp.async.wait_group 0;\n" ::);
}

// ----------------------------------------------------------------------------
// Merged projection SGEMM (unchanged from R5).
// Logical M = 1024 (queries) + 8192 (keys); N = 256, K = 256.
// BM=128, BN=128, BK=16, 256 threads, 8x8 micro-tile. Grid (2,72) = one wave.
// ----------------------------------------------------------------------------
#define PJ_PAD 132

__global__ __launch_bounds__(256, 1)
void proj_kernel(const float* __restrict__ queries,
                 const float* __restrict__ keys,
                 const float* __restrict__ Wq,
                 const float* __restrict__ Wk,
                 float* __restrict__ qh,
                 float* __restrict__ kh) {
    __shared__ float As[16 * PJ_PAD];   // [k][m] transposed, padded
    __shared__ float Ws[16 * PJ_PAD];   // [k][n], padded

    const int tid = threadIdx.x;
    const int tx  = tid & 15;
    const int ty  = tid >> 4;
    const int bm  = blockIdx.y * 128;
    const int bn  = blockIdx.x * 128;

    const float* A; const float* W; float* C; int rowbase;
    if (bm < 1024) { A = queries; W = Wq; C = qh; rowbase = bm; }
    else           { A = keys;    W = Wk; C = kh; rowbase = bm - 1024; }

    const int ar0 = tid >> 2;
    const int ac  = (tid & 3) * 4;
    const int wr0 = tid >> 5;
    const int wc  = (tid & 31) * 4;

    float acc[8][8] = {};

    for (int k0 = 0; k0 < 256; k0 += 16) {
        float4 a0 = *(const float4*)&A[(rowbase + ar0)      * 256 + k0 + ac];
        float4 a1 = *(const float4*)&A[(rowbase + ar0 + 64) * 256 + k0 + ac];
        float4 w0 = *(const float4*)&W[(k0 + wr0)     * 256 + bn + wc];
        float4 w1 = *(const float4*)&W[(k0 + wr0 + 8) * 256 + bn + wc];

        As[(ac + 0) * PJ_PAD + ar0]      = a0.x;
        As[(ac + 1) * PJ_PAD + ar0]      = a0.y;
        As[(ac + 2) * PJ_PAD + ar0]      = a0.z;
        As[(ac + 3) * PJ_PAD + ar0]      = a0.w;
        As[(ac + 0) * PJ_PAD + ar0 + 64] = a1.x;
        As[(ac + 1) * PJ_PAD + ar0 + 64] = a1.y;
        As[(ac + 2) * PJ_PAD + ar0 + 64] = a1.z;
        As[(ac + 3) * PJ_PAD + ar0 + 64] = a1.w;
        *(float4*)&Ws[ wr0      * PJ_PAD + wc] = w0;
        *(float4*)&Ws[(wr0 + 8) * PJ_PAD + wc] = w1;
        __syncthreads();

        #pragma unroll
        for (int kk = 0; kk < 16; ++kk) {
            float a[8], b[8];
            *(float4*)&a[0] = *(const float4*)&As[kk * PJ_PAD + ty * 8];
            *(float4*)&a[4] = *(const float4*)&As[kk * PJ_PAD + ty * 8 + 4];
            *(float4*)&b[0] = *(const float4*)&Ws[kk * PJ_PAD + tx * 8];
            *(float4*)&b[4] = *(const float4*)&Ws[kk * PJ_PAD + tx * 8 + 4];
            #pragma unroll
            for (int i = 0; i < 8; ++i)
                #pragma unroll
                for (int j = 0; j < 8; ++j)
                    acc[i][j] = fmaf(a[i], b[j], acc[i][j]);
        }
        __syncthreads();
    }

    #pragma unroll
    for (int i = 0; i < 8; ++i) {
        float* dst = &C[(rowbase + ty * 8 + i) * 256 + bn + tx * 8];
        *(float4*)&dst[0] = *(float4*)&acc[i][0];
        *(float4*)&dst[4] = *(float4*)&acc[i][4];
    }
}

// ----------------------------------------------------------------------------
// Fused scores + masked softmax + attn@V.
// Grid: 128 blocks = (b, 8-query tile).  Block: 512 threads = 16 warps.
// Warp w owns keys [w*32, w*32+32) (lane = one key), computes all 8 queries.
// Keys staged in h-chunks: chunk c = all 512 keys x 32 h values, stride 36
// floats (conflict-free in 8-lane phases for both cp.async STS and LDS.128).
// ----------------------------------------------------------------------------
#define KB_STRIDE 36
#define NKEY 512
#define KBUF_FLOATS (NKEY * KB_STRIDE)          // 18432 per buffer
#define ATTN_SMEM_FLOATS (2 * KBUF_FLOATS + 8 * 256 + 256 + 8 * 512 + 128 + 16)
#define ATTN_SMEM_BYTES  (ATTN_SMEM_FLOATS * 4)

__global__ __launch_bounds__(512, 1)
void attn_kernel(const float* __restrict__ values,
                 const int* __restrict__ valid_lens,
                 const float* __restrict__ w_v,
                 float* __restrict__ out) {
    extern __shared__ float sm[];
    float* kbuf   = sm;                          // 2 x 512 x 36 (double buf)
    float* qh_s   = kbuf + 2 * KBUF_FLOATS;      // 8 x 256
    float* wv_s   = qh_s + 8 * 256;              // 256
    float* attn_s = wv_s + 256;                  // 8 x 512
    float* red1   = attn_s + 8 * 512;            // 128: per-(q,warp) partials
    float* fin_s  = red1 + 128;                  // [0..7] max, [8..15] 1/sum

    const int tid  = threadIdx.x;
    const int b    = blockIdx.x >> 3;
    const int q0   = (blockIdx.x & 7) * 8;
    const int w    = tid >> 5;
    const int lane = tid & 31;
    const int key  = w * 32 + lane;             // this lane's key (fixed)
    const int vlen = valid_lens[b];

    // stage 8 query rows (one float4 per thread) and w_v
    *(float4*)&qh_s[tid * 4] =
        *(const float4*)&g_qh[((size_t)(b * 64 + q0)) * 256 + tid * 4];
    if (tid < 64)
        *(float4*)&wv_s[tid * 4] = *(const float4*)&w_v[tid * 4];

    // cp.async staging: chunk c -> kbuf[(c&1)*KBUF].  Thread tid stages the
    // 32 floats of key==tid: 8 x 16B.
    const float* khg = &g_kh[(size_t)b * 512 * 256 + (size_t)tid * 256];
    #pragma unroll
    for (int pre = 0; pre < 2; ++pre) {
        float* dst = &kbuf[pre * KBUF_FLOATS + tid * KB_STRIDE];
        const float* src = &khg[pre * 32];
        #pragma unroll
        for (int j = 0; j < 8; ++j)
            cp_async16(&dst[j * 4], &src[j * 4]);
        cp_async_commit();
    }

    float sc[8] = {0.f, 0.f, 0.f, 0.f, 0.f, 0.f, 0.f, 0.f};

    #pragma unroll 1
    for (int c = 0; c < 8; ++c) {
        if (c < 7) cp_async_wait1(); else cp_async_wait0();
        __syncthreads();

        const float* kb = &kbuf[(c & 1) * KBUF_FLOATS + key * KB_STRIDE];
        const int hbase = c * 32;

        #pragma unroll 2
        for (int i = 0; i < 8; ++i) {
            float4 kv = *(const float4*)&kb[i * 4];
            float4 w4 = *(const float4*)&wv_s[hbase + i * 4];
            #pragma unroll
            for (int q = 0; q < 8; ++q) {
                float4 qv = *(const float4*)&qh_s[q * 256 + hbase + i * 4];
                sc[q] = fmaf(w4.x, tanh_fast(qv.x + kv.x), sc[q]);
                sc[q] = fmaf(w4.y, tanh_fast(qv.y + kv.y), sc[q]);
                sc[q] = fmaf(w4.z, tanh_fast(qv.z + kv.z), sc[q]);
                sc[q] = fmaf(w4.w, tanh_fast(qv.w + kv.w), sc[q]);
            }
        }

        __syncthreads();
        if (c < 6) {   // prefetch chunk c+2 into the buffer just freed
            float* dst = &kbuf[(c & 1) * KBUF_FLOATS + tid * KB_STRIDE];
            const float* src = &khg[(c + 2) * 32];
            #pragma unroll
            for (int j = 0; j < 8; ++j)
                cp_async16(&dst[j * 4], &src[j * 4]);
            cp_async_commit();
        }
    }

    // ---- masked softmax over keys (per query) ----
    // mask + per-warp max
    #pragma unroll
    for (int q = 0; q < 8; ++q) {
        float v = sc[q];
        if (key >= vlen) v = -1e30f;
        sc[q] = v;
        #pragma unroll
        for (int o = 16; o; o >>= 1) v = fmaxf(v, __shfl_xor_sync(0xffffffffu, v, o));
        if (lane == 0) red1[q * 16 + w] = v;
    }
    __syncthreads();
    if (tid < 128) {           // 16-lane groups finalize per-q max
        const int q = tid >> 4, i = tid & 15;
        float v = red1[q * 16 + i];
        #pragma unroll
        for (int o = 8; o; o >>= 1) v = fmaxf(v, __shfl_xor_sync(0xffffffffu, v, o));
        if (i == 0) fin_s[q] = v;
    }
    __syncthreads();

    float p[8];
    #pragma unroll
    for (int q = 0; q < 8; ++q) {
        p[q] = ex2_fast((sc[q] - fin_s[q]) * 1.4426950408889634f);
        float v = p[q];
        #pragma unroll
        for (int o = 16; o; o >>= 1) v += __shfl_xor_sync(0xffffffffu, v, o);
        if (lane == 0) red1[q * 16 + w] = v;
    }
    __syncthreads();
    if (tid < 128) {
        const int q = tid >> 4, i = tid & 15;
        float v = red1[q * 16 + i];
        #pragma unroll
        for (int o = 8; o; o >>= 1) v += __shfl_xor_sync(0xffffffffu, v, o);
        if (i == 0) fin_s[8 + q] = rcp_fast(v);
    }
    __syncthreads();

    #pragma unroll
    for (int q = 0; q < 8; ++q)
        attn_s[q * 512 + key] = p[q] * fin_s[8 + q];
    __syncthreads();

    // ------ output: out[b, q0+qq, v] = sum_k attn[qq][k] * values[b,k,v] ------
    const int half = tid >> 8;          // 0: q0..q0+3, 1: q0+4..q0+7
    const int v    = tid & 255;
    const float* vp = values + (size_t)b * 512 * 256 + v;
    const float* a0 = &attn_s[(half * 4 + 0) * 512];
    const float* a1 = a0 + 512;
    const float* a2 = a1 + 512;
    const float* a3 = a2 + 512;
    float o0 = 0.f, o1 = 0.f, o2 = 0.f, o3 = 0.f;
    #pragma unroll 4
    for (int k = 0; k < vlen; ++k) {
        float vv = vp[(size_t)k * 256];
        o0 = fmaf(a0[k], vv, o0);
        o1 = fmaf(a1[k], vv, o1);
        o2 = fmaf(a2[k], vv, o2);
        o3 = fmaf(a3[k], vv, o3);
    }
    float* op = out + ((size_t)b * 64 + q0 + half * 4) * 256 + v;
    op[0]   = o0;
    op[256] = o1;
    op[512] = o2;
    op[768] = o3;
}

// ----------------------------------------------------------------------------
extern "C" void kernel_launch(void* const* d_in, const int* in_sizes, int n_in,
                              void* d_out, int out_size) {
    (void)in_sizes; (void)n_in; (void)out_size;
    const float* queries = (const float*)d_in[0];   // [16,64,256]
    const float* keys    = (const float*)d_in[1];   // [16,512,256]
    const float* values  = (const float*)d_in[2];   // [16,512,256]
    const int*   vlens   = (const int*)  d_in[3];   // [16]
    const float* Wq      = (const float*)d_in[4];   // [256,256]
    const float* Wk      = (const float*)d_in[5];   // [256,256]
    const float* wv      = (const float*)d_in[6];   // [256]
    float* out = (float*)d_out;                     // [16,64,256]

    float *qh = nullptr, *kh = nullptr;
    cudaGetSymbolAddress((void**)&qh, g_qh);
    cudaGetSymbolAddress((void**)&kh, g_kh);

    cudaFuncSetAttribute(attn_kernel,
                         cudaFuncAttributeMaxDynamicSharedMemorySize,
                         ATTN_SMEM_BYTES);

    proj_kernel<<<dim3(2, 72), 256>>>(queries, keys, Wq, Wk, qh, kh);
    attn_kernel<<<128, 512, ATTN_SMEM_BYTES>>>(values, vlens, wv, out);
}